// round 1
// baseline (speedup 1.0000x reference)
#include <cuda_runtime.h>
#include <math.h>

// Problem constants
#define BB   2
#define SS   2048
#define DIN  2048
#define NH   8
#define NKV  4
#define HD   256
#define QDIM  (NH*HD)    // 2048
#define KVDIM (NKV*HD)   // 1024
#define SCALING 0.0625f  // 256^-0.5
#define EPS 1e-6f

// Scratch (device globals: no runtime allocation allowed)
__device__ float g_q[(size_t)BB*SS*QDIM];
__device__ float g_k[(size_t)BB*SS*KVDIM];
__device__ float g_v[(size_t)BB*SS*KVDIM];
__device__ float g_ctx[(size_t)BB*SS*QDIM];

// ---------------------------------------------------------------------------
// SGEMM (NT): C[M,N] = A[M,K] @ B[N,K]^T.  Both operands K-contiguous.
// 128x128 tile, BK=16, 256 threads, 8x8 per thread (4+4 split for
// conflict-free float4 smem reads).
// ---------------------------------------------------------------------------
#define GBM 128
#define GBN 128
#define GBK 16

__global__ __launch_bounds__(256, 2)
void sgemm_nt(const float* __restrict__ A, const float* __restrict__ Bw,
              float* __restrict__ C, int M, int N, int K) {
    __shared__ float As[GBK * GBM];
    __shared__ float Bs[GBK * GBN];

    const int bx = blockIdx.x;   // N tile
    const int by = blockIdx.y;   // M tile
    const int tid = threadIdx.x;
    const int tx = tid & 15;
    const int ty = tid >> 4;

    const float* Ab = A  + (size_t)by * GBM * K;
    const float* Bb = Bw + (size_t)bx * GBN * K;

    float acc[8][8];
#pragma unroll
    for (int i = 0; i < 8; i++)
#pragma unroll
        for (int j = 0; j < 8; j++) acc[i][j] = 0.f;

    for (int k0 = 0; k0 < K; k0 += GBK) {
        // load 128x16 tiles (512 float4 each), id = tid + 256*it
#pragma unroll
        for (int it = 0; it < 2; it++) {
            int id  = tid + 256 * it;          // 0..511
            int row = id >> 2;                 // 4 float4 per row
            int c4  = (id & 3) << 2;
            float4 a = *(const float4*)(Ab + (size_t)row * K + k0 + c4);
            As[(c4 + 0) * GBM + row] = a.x;
            As[(c4 + 1) * GBM + row] = a.y;
            As[(c4 + 2) * GBM + row] = a.z;
            As[(c4 + 3) * GBM + row] = a.w;
            float4 b = *(const float4*)(Bb + (size_t)row * K + k0 + c4);
            Bs[(c4 + 0) * GBN + row] = b.x;
            Bs[(c4 + 1) * GBN + row] = b.y;
            Bs[(c4 + 2) * GBN + row] = b.z;
            Bs[(c4 + 3) * GBN + row] = b.w;
        }
        __syncthreads();

#pragma unroll
        for (int kk = 0; kk < GBK; kk++) {
            float ar[8], br[8];
            float4 a0 = *(const float4*)&As[kk * GBM + ty * 4];
            float4 a1 = *(const float4*)&As[kk * GBM + 64 + ty * 4];
            ar[0]=a0.x; ar[1]=a0.y; ar[2]=a0.z; ar[3]=a0.w;
            ar[4]=a1.x; ar[5]=a1.y; ar[6]=a1.z; ar[7]=a1.w;
            float4 b0 = *(const float4*)&Bs[kk * GBN + tx * 4];
            float4 b1 = *(const float4*)&Bs[kk * GBN + 64 + tx * 4];
            br[0]=b0.x; br[1]=b0.y; br[2]=b0.z; br[3]=b0.w;
            br[4]=b1.x; br[5]=b1.y; br[6]=b1.z; br[7]=b1.w;
#pragma unroll
            for (int i = 0; i < 8; i++)
#pragma unroll
                for (int j = 0; j < 8; j++)
                    acc[i][j] += ar[i] * br[j];
        }
        __syncthreads();
    }

    // write back: rows {by*128 + ty*4+i, +64}, cols {bx*128 + tx*4+j, +64}
    const int row0 = by * GBM + ty * 4;
    const int col0 = bx * GBN + tx * 4;
#pragma unroll
    for (int u = 0; u < 4; u++) {
        float4 v;
        v.x=acc[u][0]; v.y=acc[u][1]; v.z=acc[u][2]; v.w=acc[u][3];
        *(float4*)(C + (size_t)(row0 + u) * N + col0) = v;
        v.x=acc[u][4]; v.y=acc[u][5]; v.z=acc[u][6]; v.w=acc[u][7];
        *(float4*)(C + (size_t)(row0 + u) * N + col0 + 64) = v;
        v.x=acc[4+u][0]; v.y=acc[4+u][1]; v.z=acc[4+u][2]; v.w=acc[4+u][3];
        *(float4*)(C + (size_t)(row0 + 64 + u) * N + col0) = v;
        v.x=acc[4+u][4]; v.y=acc[4+u][5]; v.z=acc[4+u][6]; v.w=acc[4+u][7];
        *(float4*)(C + (size_t)(row0 + 64 + u) * N + col0 + 64) = v;
    }
}

// ---------------------------------------------------------------------------
// Fused RMSNorm + RoPE (+ q scaling). One block per (b,s,head) row of 256.
// blockIdx.x = b*S+s (0..4095), blockIdx.y = head (0..7 -> q, 8..11 -> k).
// ---------------------------------------------------------------------------
__global__ void rms_rope(const float* __restrict__ cosp,
                         const float* __restrict__ sinp,
                         const float* __restrict__ q_gamma,
                         const float* __restrict__ k_gamma) {
    __shared__ float red[8];
    __shared__ float xn_s[HD];

    const int bs = blockIdx.x;          // b*S + s
    const int hh = blockIdx.y;
    const int spos = bs & (SS - 1);
    const int d = threadIdx.x;

    float* ptr;
    const float* gamma;
    float scale;
    if (hh < NH) {
        ptr = g_q + (size_t)bs * QDIM + hh * HD;
        gamma = q_gamma;
        scale = SCALING;
    } else {
        ptr = g_k + (size_t)bs * KVDIM + (hh - NH) * HD;
        gamma = k_gamma;
        scale = 1.0f;
    }

    float v = ptr[d];
    float ss = v * v;
#pragma unroll
    for (int off = 16; off >= 1; off >>= 1)
        ss += __shfl_xor_sync(0xffffffffu, ss, off);
    if ((d & 31) == 0) red[d >> 5] = ss;
    __syncthreads();
    if (d < 8) {
        float t = red[d];
#pragma unroll
        for (int off = 4; off >= 1; off >>= 1)
            t += __shfl_xor_sync(0xffu, t, off);
        if (d == 0) red[0] = t;
    }
    __syncthreads();
    float rstd = rsqrtf(red[0] * (1.0f / HD) + EPS);

    float xn = v * rstd * (1.0f + gamma[d]);
    xn_s[d] = xn;
    __syncthreads();
    float rot = (d < HD / 2) ? -xn_s[d + HD / 2] : xn_s[d - HD / 2];
    float out = (xn * cosp[(size_t)spos * HD + d] + rot * sinp[(size_t)spos * HD + d]) * scale;
    ptr[d] = out;
}

// ---------------------------------------------------------------------------
// Flash attention (fp32, causal). BM=BN=64, D=256, 256 threads (16x16).
// Thread (ty,tx) owns S/O rows {ty+16i, i<4}, S cols {tx+16j, j<4},
// O dims {tx+16j, j<16}. Conflict-free smem via 257-pitch for Q/K.
// ---------------------------------------------------------------------------
#define FQ_PITCH 257
#define FP_PITCH 68
#define SMEM_Q  0
#define SMEM_K  (64 * FQ_PITCH)
#define SMEM_V  (2 * 64 * FQ_PITCH)
#define SMEM_P  (2 * 64 * FQ_PITCH + 64 * HD)
#define FLASH_SMEM_FLOATS (2 * 64 * FQ_PITCH + 64 * HD + 64 * FP_PITCH)

__global__ __launch_bounds__(256, 1)
void flash_fp32() {
    extern __shared__ float sm[];
    float* Qs = sm + SMEM_Q;
    float* Ks = sm + SMEM_K;
    float* Vs = sm + SMEM_V;
    float* Ps = sm + SMEM_P;

    const int qt = blockIdx.x;
    const int h  = blockIdx.y;
    const int b  = blockIdx.z;
    const int kvh = h >> 1;
    const int tid = threadIdx.x;
    const int tx = tid & 15;
    const int ty = tid >> 4;
    const int q0 = qt * 64;

    // load Q tile [64][256] into pitched smem
#pragma unroll
    for (int it = 0; it < 16; it++) {
        int id  = tid + 256 * it;        // float4 id, 0..4095
        int row = id >> 6;
        int c4  = (id & 63) << 2;
        float4 a = *(const float4*)(g_q + (size_t)(b * SS + q0 + row) * QDIM + h * HD + c4);
        float* dst = Qs + row * FQ_PITCH + c4;
        dst[0]=a.x; dst[1]=a.y; dst[2]=a.z; dst[3]=a.w;
    }

    float acc[4][16];
#pragma unroll
    for (int i = 0; i < 4; i++)
#pragma unroll
        for (int j = 0; j < 16; j++) acc[i][j] = 0.f;
    float mrow[4] = {-1e30f, -1e30f, -1e30f, -1e30f};
    float lrow[4] = {0.f, 0.f, 0.f, 0.f};

    for (int kt = 0; kt <= qt; kt++) {
        const int k0 = kt * 64;
        __syncthreads();   // prior-iter smem reads done (also covers Q stores, iter 0)
        // load K,V tiles
#pragma unroll
        for (int it = 0; it < 16; it++) {
            int id  = tid + 256 * it;
            int row = id >> 6;
            int c4  = (id & 63) << 2;
            size_t gofs = (size_t)(b * SS + k0 + row) * KVDIM + kvh * HD + c4;
            float4 kk4 = *(const float4*)(g_k + gofs);
            float* kd = Ks + row * FQ_PITCH + c4;
            kd[0]=kk4.x; kd[1]=kk4.y; kd[2]=kk4.z; kd[3]=kk4.w;
            float4 vv4 = *(const float4*)(g_v + gofs);
            *(float4*)(Vs + row * HD + c4) = vv4;
        }
        __syncthreads();

        // phase A: S = Q @ K^T (4x4 per thread)
        float s[4][4];
#pragma unroll
        for (int i = 0; i < 4; i++)
#pragma unroll
            for (int j = 0; j < 4; j++) s[i][j] = 0.f;

#pragma unroll 4
        for (int kk = 0; kk < HD; kk++) {
            float a_[4], b_[4];
#pragma unroll
            for (int i = 0; i < 4; i++) a_[i] = Qs[(ty + 16 * i) * FQ_PITCH + kk];
#pragma unroll
            for (int j = 0; j < 4; j++) b_[j] = Ks[(tx + 16 * j) * FQ_PITCH + kk];
#pragma unroll
            for (int i = 0; i < 4; i++)
#pragma unroll
                for (int j = 0; j < 4; j++)
                    s[i][j] += a_[i] * b_[j];
        }

        if (kt == qt) {
#pragma unroll
            for (int i = 0; i < 4; i++)
#pragma unroll
                for (int j = 0; j < 4; j++)
                    if (k0 + tx + 16 * j > q0 + ty + 16 * i) s[i][j] = -1e30f;
        }

        // online softmax per owned row (16-lane half-warp reductions)
#pragma unroll
        for (int i = 0; i < 4; i++) {
            float mt = fmaxf(fmaxf(s[i][0], s[i][1]), fmaxf(s[i][2], s[i][3]));
#pragma unroll
            for (int off = 8; off >= 1; off >>= 1)
                mt = fmaxf(mt, __shfl_xor_sync(0xffffffffu, mt, off));
            float mnew = fmaxf(mrow[i], mt);
            float alpha = __expf(mrow[i] - mnew);
            mrow[i] = mnew;
            float rs = 0.f;
#pragma unroll
            for (int j = 0; j < 4; j++) {
                float p = __expf(s[i][j] - mnew);
                s[i][j] = p;
                rs += p;
            }
#pragma unroll
            for (int off = 8; off >= 1; off >>= 1)
                rs += __shfl_xor_sync(0xffffffffu, rs, off);
            lrow[i] = lrow[i] * alpha + rs;
#pragma unroll
            for (int j = 0; j < 16; j++) acc[i][j] *= alpha;
#pragma unroll
            for (int j = 0; j < 4; j++)
                Ps[(ty + 16 * i) * FP_PITCH + tx + 16 * j] = s[i][j];
        }
        __syncthreads();

        // phase B: O += P @ V
#pragma unroll 2
        for (int c = 0; c < 64; c++) {
            float p_[4];
#pragma unroll
            for (int i = 0; i < 4; i++) p_[i] = Ps[(ty + 16 * i) * FP_PITCH + c];
#pragma unroll
            for (int j = 0; j < 16; j++) {
                float v = Vs[c * HD + tx + 16 * j];
#pragma unroll
                for (int i = 0; i < 4; i++) acc[i][j] += p_[i] * v;
            }
        }
    }

    // epilogue: normalize and store ctx
#pragma unroll
    for (int i = 0; i < 4; i++) {
        float inv = 1.0f / lrow[i];
        size_t base = (size_t)(b * SS + q0 + ty + 16 * i) * QDIM + h * HD + tx;
#pragma unroll
        for (int j = 0; j < 16; j++)
            g_ctx[base + 16 * j] = acc[i][j] * inv;
    }
}

// ---------------------------------------------------------------------------
// launch
// ---------------------------------------------------------------------------
extern "C" void kernel_launch(void* const* d_in, const int* in_sizes, int n_in,
                              void* d_out, int out_size) {
    const float* x    = (const float*)d_in[0];
    // d_in[1] = mask (bool) — causal, recomputed in-kernel
    const float* cosp = (const float*)d_in[2];
    const float* sinp = (const float*)d_in[3];
    const float* wq   = (const float*)d_in[4];
    const float* wk   = (const float*)d_in[5];
    const float* wv   = (const float*)d_in[6];
    const float* wo   = (const float*)d_in[7];
    const float* qg   = (const float*)d_in[8];
    const float* kg   = (const float*)d_in[9];
    float* out = (float*)d_out;

    float *pq, *pk, *pv, *pctx;
    cudaGetSymbolAddress((void**)&pq,   g_q);
    cudaGetSymbolAddress((void**)&pk,   g_k);
    cudaGetSymbolAddress((void**)&pv,   g_v);
    cudaGetSymbolAddress((void**)&pctx, g_ctx);

    const int M = BB * SS;   // 4096

    // QKV projections
    sgemm_nt<<<dim3(QDIM / GBN,  M / GBM), 256>>>(x, wq, pq, M, QDIM,  DIN);
    sgemm_nt<<<dim3(KVDIM / GBN, M / GBM), 256>>>(x, wk, pk, M, KVDIM, DIN);
    sgemm_nt<<<dim3(KVDIM / GBN, M / GBM), 256>>>(x, wv, pv, M, KVDIM, DIN);

    // RMSNorm + RoPE (+ q scaling)
    rms_rope<<<dim3(M, NH + NKV), HD>>>(cosp, sinp, qg, kg);

    // Flash attention
    static const size_t flash_smem = FLASH_SMEM_FLOATS * sizeof(float);
    cudaFuncSetAttribute(flash_fp32, cudaFuncAttributeMaxDynamicSharedMemorySize,
                         (int)flash_smem);
    flash_fp32<<<dim3(SS / 64, NH, BB), 256, flash_smem>>>();

    // Output projection
    sgemm_nt<<<dim3(QDIM / GBN, M / GBM), 256>>>(pctx, wo, out, M, QDIM, DIN);
}

// round 3
// speedup vs baseline: 1.5646x; 1.5646x over previous
#include <cuda_runtime.h>
#include <cuda_bf16.h>
#include <cstdint>
#include <math.h>

// Problem constants
#define BB   2
#define SS   2048
#define DIN  2048
#define NH   8
#define NKV  4
#define HD   256
#define QDIM  (NH*HD)    // 2048
#define KVDIM (NKV*HD)   // 1024
#define SCALING 0.0625f  // 256^-0.5
#define EPS 1e-6f

// ---------------------------------------------------------------------------
// Scratch (device globals: no runtime allocation allowed)
// ---------------------------------------------------------------------------
__device__ float g_q[(size_t)BB*SS*QDIM];
__device__ float g_k[(size_t)BB*SS*KVDIM];
__device__ float g_v[(size_t)BB*SS*KVDIM];
__device__ float g_ctx[(size_t)BB*SS*QDIM];

// bf16 hi/lo split buffers
__device__ __nv_bfloat16 g_xh[(size_t)BB*SS*DIN];
__device__ __nv_bfloat16 g_xl[(size_t)BB*SS*DIN];
__device__ __nv_bfloat16 g_wqh[(size_t)QDIM*DIN];
__device__ __nv_bfloat16 g_wql[(size_t)QDIM*DIN];
__device__ __nv_bfloat16 g_wkh[(size_t)KVDIM*DIN];
__device__ __nv_bfloat16 g_wkl[(size_t)KVDIM*DIN];
__device__ __nv_bfloat16 g_wvh[(size_t)KVDIM*DIN];
__device__ __nv_bfloat16 g_wvl[(size_t)KVDIM*DIN];
__device__ __nv_bfloat16 g_woh[(size_t)DIN*QDIM];
__device__ __nv_bfloat16 g_wol[(size_t)DIN*QDIM];
__device__ __nv_bfloat16 g_ch[(size_t)BB*SS*QDIM];
__device__ __nv_bfloat16 g_cl[(size_t)BB*SS*QDIM];

// ---------------------------------------------------------------------------
// Helpers
// ---------------------------------------------------------------------------
__device__ __forceinline__ uint32_t smem_to_u32(const void* smem_ptr) {
    uint32_t addr;
    asm("{ .reg .u64 tmp; cvta.to.shared.u64 tmp, %1; cvt.u32.u64 %0, tmp; }"
        : "=r"(addr) : "l"(smem_ptr));
    return addr;
}

__device__ __forceinline__ void ldsm_x4(uint32_t& r0, uint32_t& r1,
                                        uint32_t& r2, uint32_t& r3, uint32_t addr) {
    asm volatile("ldmatrix.sync.aligned.m8n8.x4.shared.b16 {%0,%1,%2,%3}, [%4];"
                 : "=r"(r0), "=r"(r1), "=r"(r2), "=r"(r3) : "r"(addr));
}
__device__ __forceinline__ void ldsm_x2(uint32_t& r0, uint32_t& r1, uint32_t addr) {
    asm volatile("ldmatrix.sync.aligned.m8n8.x2.shared.b16 {%0,%1}, [%2];"
                 : "=r"(r0), "=r"(r1) : "r"(addr));
}
__device__ __forceinline__ void mma_bf16(float* d, const uint32_t* a, const uint32_t* b) {
    asm volatile(
        "mma.sync.aligned.m16n8k16.row.col.f32.bf16.bf16.f32 "
        "{%0,%1,%2,%3}, {%4,%5,%6,%7}, {%8,%9}, {%0,%1,%2,%3};"
        : "+f"(d[0]), "+f"(d[1]), "+f"(d[2]), "+f"(d[3])
        : "r"(a[0]), "r"(a[1]), "r"(a[2]), "r"(a[3]), "r"(b[0]), "r"(b[1]));
}
__device__ __forceinline__ void cp_async16(uint32_t dst, const void* src) {
    asm volatile("cp.async.cg.shared.global [%0], [%1], 16;"
                 :: "r"(dst), "l"(src));
}

// ---------------------------------------------------------------------------
// Split fp32 -> bf16 hi + bf16 lo (residual). Vectorized by 4.
// ---------------------------------------------------------------------------
__device__ __forceinline__ void split1(float v, unsigned short& h, unsigned short& l) {
    __nv_bfloat16 bh = __float2bfloat16(v);
    float r = v - __bfloat162float(bh);
    __nv_bfloat16 bl = __float2bfloat16(r);
    h = __bfloat16_as_ushort(bh);
    l = __bfloat16_as_ushort(bl);
}

__global__ void split_f32(const float* __restrict__ x,
                          __nv_bfloat16* __restrict__ hi,
                          __nv_bfloat16* __restrict__ lo, int n4) {
    int i = blockIdx.x * blockDim.x + threadIdx.x;
    if (i >= n4) return;
    float4 v = ((const float4*)x)[i];
    ushort4 h, l;
    split1(v.x, h.x, l.x);
    split1(v.y, h.y, l.y);
    split1(v.z, h.z, l.z);
    split1(v.w, h.w, l.w);
    ((ushort4*)hi)[i] = h;
    ((ushort4*)lo)[i] = l;
}

// ---------------------------------------------------------------------------
// HMMA GEMM (NT): C[M,N] = A[M,K] @ B[N,K]^T with bf16 hi/lo 3-term split.
// Tile 128x128, BK=32, 8 warps (2x4), warp tile 64x32, m16n8k16.
// smem: 2 stages x {Ah, Al, Bh, Bl}, each 128 rows x 80B pitch (32 halves used).
// cp.async double-buffered.
// ---------------------------------------------------------------------------
#define HBK 32
#define HPITCH 80                      // bytes per smem row
#define HMAT_BYTES (128 * HPITCH)      // 10240
#define HSTAGE_BYTES (4 * HMAT_BYTES)  // 40960
#define HSMEM_BYTES (2 * HSTAGE_BYTES) // 81920

__global__ __launch_bounds__(256, 2)
void gemm_hmma3(const __nv_bfloat16* __restrict__ Ah,
                const __nv_bfloat16* __restrict__ Al,
                const __nv_bfloat16* __restrict__ Bh,
                const __nv_bfloat16* __restrict__ Bl,
                float* __restrict__ C, int M, int N, int K) {
    extern __shared__ char smemc[];
    const uint32_t smem = smem_to_u32(smemc);
    const int tid = threadIdx.x;
    const int wid = tid >> 5;
    const int lid = tid & 31;
    const int warp_m = wid >> 2;     // 0-1
    const int warp_n = wid & 3;      // 0-3
    const int m0 = blockIdx.y * 128;
    const int n0 = blockIdx.x * 128;
    const int kchunks = K / HBK;

    // per-thread prefetch geometry: 8 granules of 16B
    // g = tid + 256*it ; mat = g>>9 (0:Ah 1:Al 2:Bh 3:Bl); idx=g&511; r=idx>>2; q=idx&3
    const __nv_bfloat16* srcs[4] = {Ah, Al, Bh, Bl};

#define PREFETCH(cc) do {                                                     \
        const int s_ = (cc) & 1;                                              \
        const int k0_ = (cc) * HBK;                                           \
        _Pragma("unroll")                                                     \
        for (int it = 0; it < 8; it++) {                                      \
            int g = tid + 256 * it;                                           \
            int mat = g >> 9;                                                 \
            int idx = g & 511;                                                \
            int r = idx >> 2;                                                 \
            int q = idx & 3;                                                  \
            int rowg = (mat < 2 ? m0 : n0) + r;                               \
            const __nv_bfloat16* src = srcs[mat] + (size_t)rowg * K + k0_ + q * 8; \
            uint32_t dst = smem + s_ * HSTAGE_BYTES + mat * HMAT_BYTES        \
                         + r * HPITCH + q * 16;                               \
            cp_async16(dst, src);                                             \
        }                                                                     \
        asm volatile("cp.async.commit_group;");                               \
    } while (0)

    float acc[4][4][4];
#pragma unroll
    for (int i = 0; i < 4; i++)
#pragma unroll
        for (int j = 0; j < 4; j++)
#pragma unroll
            for (int q = 0; q < 4; q++) acc[i][j][q] = 0.f;

    PREFETCH(0);

    for (int c = 0; c < kchunks; c++) {
        if (c + 1 < kchunks) {
            PREFETCH(c + 1);
            asm volatile("cp.async.wait_group 1;" ::: "memory");
        } else {
            asm volatile("cp.async.wait_group 0;" ::: "memory");
        }
        __syncthreads();

        const uint32_t stage = smem + (c & 1) * HSTAGE_BYTES;
        const uint32_t sAh = stage;
        const uint32_t sAl = stage + HMAT_BYTES;
        const uint32_t sBh = stage + 2 * HMAT_BYTES;
        const uint32_t sBl = stage + 3 * HMAT_BYTES;

#pragma unroll
        for (int k16 = 0; k16 < 2; k16++) {
            const int coff = k16 * 16;   // halves
            // B fragments (hi and lo) for all 4 n-frags
            uint32_t bh[4][2], bl[4][2];
            {
                int i15 = lid & 15;
                int rb = warp_n * 32 + (i15 & 7);
                int kb = coff + ((i15 >> 3) & 1) * 8;
#pragma unroll
                for (int j = 0; j < 4; j++) {
                    uint32_t off = (uint32_t)((rb + j * 8) * HPITCH + kb * 2);
                    ldsm_x2(bh[j][0], bh[j][1], sBh + off);
                    ldsm_x2(bl[j][0], bl[j][1], sBl + off);
                }
            }
            // A hi fragments
            uint32_t a[4][4];
            {
                int ra = warp_m * 64 + (lid & 15);
                int ka = coff + (lid >> 4) * 8;
#pragma unroll
                for (int i = 0; i < 4; i++) {
                    uint32_t off = (uint32_t)((ra + i * 16) * HPITCH + ka * 2);
                    ldsm_x4(a[i][0], a[i][1], a[i][2], a[i][3], sAh + off);
                }
            }
#pragma unroll
            for (int i = 0; i < 4; i++)
#pragma unroll
                for (int j = 0; j < 4; j++) {
                    mma_bf16(acc[i][j], a[i], bh[j]);
                    mma_bf16(acc[i][j], a[i], bl[j]);
                }
            // A lo fragments (overwrite a)
            {
                int ra = warp_m * 64 + (lid & 15);
                int ka = coff + (lid >> 4) * 8;
#pragma unroll
                for (int i = 0; i < 4; i++) {
                    uint32_t off = (uint32_t)((ra + i * 16) * HPITCH + ka * 2);
                    ldsm_x4(a[i][0], a[i][1], a[i][2], a[i][3], sAl + off);
                }
            }
#pragma unroll
            for (int i = 0; i < 4; i++)
#pragma unroll
                for (int j = 0; j < 4; j++)
                    mma_bf16(acc[i][j], a[i], bh[j]);
        }
        __syncthreads();
    }

    // epilogue
    const int rbase = m0 + warp_m * 64 + (lid >> 2);
    const int cbase = n0 + warp_n * 32 + (lid & 3) * 2;
#pragma unroll
    for (int i = 0; i < 4; i++)
#pragma unroll
        for (int j = 0; j < 4; j++) {
            float* p0 = C + (size_t)(rbase + i * 16) * N + cbase + j * 8;
            float* p1 = C + (size_t)(rbase + i * 16 + 8) * N + cbase + j * 8;
            *(float2*)p0 = make_float2(acc[i][j][0], acc[i][j][1]);
            *(float2*)p1 = make_float2(acc[i][j][2], acc[i][j][3]);
        }
#undef PREFETCH
}

// ---------------------------------------------------------------------------
// Fused RMSNorm + RoPE (+ q scaling).
// ---------------------------------------------------------------------------
__global__ void rms_rope(const float* __restrict__ cosp,
                         const float* __restrict__ sinp,
                         const float* __restrict__ q_gamma,
                         const float* __restrict__ k_gamma) {
    __shared__ float red[8];
    __shared__ float xn_s[HD];

    const int bs = blockIdx.x;
    const int hh = blockIdx.y;
    const int spos = bs & (SS - 1);
    const int d = threadIdx.x;

    float* ptr;
    const float* gamma;
    float scale;
    if (hh < NH) {
        ptr = g_q + (size_t)bs * QDIM + hh * HD;
        gamma = q_gamma;
        scale = SCALING;
    } else {
        ptr = g_k + (size_t)bs * KVDIM + (hh - NH) * HD;
        gamma = k_gamma;
        scale = 1.0f;
    }

    float v = ptr[d];
    float ss = v * v;
#pragma unroll
    for (int off = 16; off >= 1; off >>= 1)
        ss += __shfl_xor_sync(0xffffffffu, ss, off);
    if ((d & 31) == 0) red[d >> 5] = ss;
    __syncthreads();
    if (d < 8) {
        float t = red[d];
#pragma unroll
        for (int off = 4; off >= 1; off >>= 1)
            t += __shfl_xor_sync(0xffu, t, off);
        if (d == 0) red[0] = t;
    }
    __syncthreads();
    float rstd = rsqrtf(red[0] * (1.0f / HD) + EPS);

    float xn = v * rstd * (1.0f + gamma[d]);
    xn_s[d] = xn;
    __syncthreads();
    float rot = (d < HD / 2) ? -xn_s[d + HD / 2] : xn_s[d - HD / 2];
    float out = (xn * cosp[(size_t)spos * HD + d] + rot * sinp[(size_t)spos * HD + d]) * scale;
    ptr[d] = out;
}

// ---------------------------------------------------------------------------
// Flash attention (fp32, causal). BM=BN=64, D=256, 256 threads (16x16).
// ---------------------------------------------------------------------------
#define FQ_PITCH 257
#define FP_PITCH 68
#define SMEM_Q  0
#define SMEM_K  (64 * FQ_PITCH)
#define SMEM_V  (2 * 64 * FQ_PITCH)
#define SMEM_P  (2 * 64 * FQ_PITCH + 64 * HD)
#define FLASH_SMEM_FLOATS (2 * 64 * FQ_PITCH + 64 * HD + 64 * FP_PITCH)

__global__ __launch_bounds__(256, 1)
void flash_fp32() {
    extern __shared__ float sm[];
    float* Qs = sm + SMEM_Q;
    float* Ks = sm + SMEM_K;
    float* Vs = sm + SMEM_V;
    float* Ps = sm + SMEM_P;

    const int qt = blockIdx.x;
    const int h  = blockIdx.y;
    const int b  = blockIdx.z;
    const int kvh = h >> 1;
    const int tid = threadIdx.x;
    const int tx = tid & 15;
    const int ty = tid >> 4;
    const int q0 = qt * 64;

#pragma unroll
    for (int it = 0; it < 16; it++) {
        int id  = tid + 256 * it;
        int row = id >> 6;
        int c4  = (id & 63) << 2;
        float4 a = *(const float4*)(g_q + (size_t)(b * SS + q0 + row) * QDIM + h * HD + c4);
        float* dst = Qs + row * FQ_PITCH + c4;
        dst[0]=a.x; dst[1]=a.y; dst[2]=a.z; dst[3]=a.w;
    }

    float acc[4][16];
#pragma unroll
    for (int i = 0; i < 4; i++)
#pragma unroll
        for (int j = 0; j < 16; j++) acc[i][j] = 0.f;
    float mrow[4] = {-1e30f, -1e30f, -1e30f, -1e30f};
    float lrow[4] = {0.f, 0.f, 0.f, 0.f};

    for (int kt = 0; kt <= qt; kt++) {
        const int k0 = kt * 64;
        __syncthreads();
#pragma unroll
        for (int it = 0; it < 16; it++) {
            int id  = tid + 256 * it;
            int row = id >> 6;
            int c4  = (id & 63) << 2;
            size_t gofs = (size_t)(b * SS + k0 + row) * KVDIM + kvh * HD + c4;
            float4 kk4 = *(const float4*)(g_k + gofs);
            float* kd = Ks + row * FQ_PITCH + c4;
            kd[0]=kk4.x; kd[1]=kk4.y; kd[2]=kk4.z; kd[3]=kk4.w;
            float4 vv4 = *(const float4*)(g_v + gofs);
            *(float4*)(Vs + row * HD + c4) = vv4;
        }
        __syncthreads();

        float s[4][4];
#pragma unroll
        for (int i = 0; i < 4; i++)
#pragma unroll
            for (int j = 0; j < 4; j++) s[i][j] = 0.f;

#pragma unroll 4
        for (int kk = 0; kk < HD; kk++) {
            float a_[4], b_[4];
#pragma unroll
            for (int i = 0; i < 4; i++) a_[i] = Qs[(ty + 16 * i) * FQ_PITCH + kk];
#pragma unroll
            for (int j = 0; j < 4; j++) b_[j] = Ks[(tx + 16 * j) * FQ_PITCH + kk];
#pragma unroll
            for (int i = 0; i < 4; i++)
#pragma unroll
                for (int j = 0; j < 4; j++)
                    s[i][j] += a_[i] * b_[j];
        }

        if (kt == qt) {
#pragma unroll
            for (int i = 0; i < 4; i++)
#pragma unroll
                for (int j = 0; j < 4; j++)
                    if (k0 + tx + 16 * j > q0 + ty + 16 * i) s[i][j] = -1e30f;
        }

#pragma unroll
        for (int i = 0; i < 4; i++) {
            float mt = fmaxf(fmaxf(s[i][0], s[i][1]), fmaxf(s[i][2], s[i][3]));
#pragma unroll
            for (int off = 8; off >= 1; off >>= 1)
                mt = fmaxf(mt, __shfl_xor_sync(0xffffffffu, mt, off));
            float mnew = fmaxf(mrow[i], mt);
            float alpha = __expf(mrow[i] - mnew);
            mrow[i] = mnew;
            float rs = 0.f;
#pragma unroll
            for (int j = 0; j < 4; j++) {
                float p = __expf(s[i][j] - mnew);
                s[i][j] = p;
                rs += p;
            }
#pragma unroll
            for (int off = 8; off >= 1; off >>= 1)
                rs += __shfl_xor_sync(0xffffffffu, rs, off);
            lrow[i] = lrow[i] * alpha + rs;
#pragma unroll
            for (int j = 0; j < 16; j++) acc[i][j] *= alpha;
#pragma unroll
            for (int j = 0; j < 4; j++)
                Ps[(ty + 16 * i) * FP_PITCH + tx + 16 * j] = s[i][j];
        }
        __syncthreads();

#pragma unroll 2
        for (int c = 0; c < 64; c++) {
            float p_[4];
#pragma unroll
            for (int i = 0; i < 4; i++) p_[i] = Ps[(ty + 16 * i) * FP_PITCH + c];
#pragma unroll
            for (int j = 0; j < 16; j++) {
                float v = Vs[c * HD + tx + 16 * j];
#pragma unroll
                for (int i = 0; i < 4; i++) acc[i][j] += p_[i] * v;
            }
        }
    }

#pragma unroll
    for (int i = 0; i < 4; i++) {
        float inv = 1.0f / lrow[i];
        size_t base = (size_t)(b * SS + q0 + ty + 16 * i) * QDIM + h * HD + tx;
#pragma unroll
        for (int j = 0; j < 16; j++)
            g_ctx[base + 16 * j] = acc[i][j] * inv;
    }
}

// ---------------------------------------------------------------------------
// launch
// ---------------------------------------------------------------------------
extern "C" void kernel_launch(void* const* d_in, const int* in_sizes, int n_in,
                              void* d_out, int out_size) {
    const float* x    = (const float*)d_in[0];
    const float* cosp = (const float*)d_in[2];
    const float* sinp = (const float*)d_in[3];
    const float* wq   = (const float*)d_in[4];
    const float* wk   = (const float*)d_in[5];
    const float* wv   = (const float*)d_in[6];
    const float* wo   = (const float*)d_in[7];
    const float* qg   = (const float*)d_in[8];
    const float* kg   = (const float*)d_in[9];
    float* out = (float*)d_out;

    float *pq, *pk, *pv, *pctx;
    __nv_bfloat16 *pxh, *pxl, *pwqh, *pwql, *pwkh, *pwkl, *pwvh, *pwvl, *pwoh, *pwol, *pch, *pcl;
    cudaGetSymbolAddress((void**)&pq,   g_q);
    cudaGetSymbolAddress((void**)&pk,   g_k);
    cudaGetSymbolAddress((void**)&pv,   g_v);
    cudaGetSymbolAddress((void**)&pctx, g_ctx);
    cudaGetSymbolAddress((void**)&pxh,  g_xh);
    cudaGetSymbolAddress((void**)&pxl,  g_xl);
    cudaGetSymbolAddress((void**)&pwqh, g_wqh);
    cudaGetSymbolAddress((void**)&pwql, g_wql);
    cudaGetSymbolAddress((void**)&pwkh, g_wkh);
    cudaGetSymbolAddress((void**)&pwkl, g_wkl);
    cudaGetSymbolAddress((void**)&pwvh, g_wvh);
    cudaGetSymbolAddress((void**)&pwvl, g_wvl);
    cudaGetSymbolAddress((void**)&pwoh, g_woh);
    cudaGetSymbolAddress((void**)&pwol, g_wol);
    cudaGetSymbolAddress((void**)&pch,  g_ch);
    cudaGetSymbolAddress((void**)&pcl,  g_cl);

    const int M = BB * SS;   // 4096

    cudaFuncSetAttribute(gemm_hmma3, cudaFuncAttributeMaxDynamicSharedMemorySize,
                         HSMEM_BYTES);
    cudaFuncSetAttribute(flash_fp32, cudaFuncAttributeMaxDynamicSharedMemorySize,
                         (int)(FLASH_SMEM_FLOATS * sizeof(float)));

    // splits
    {
        int n4;
        n4 = (M * DIN) / 4;      split_f32<<<(n4 + 255) / 256, 256>>>(x,  pxh,  pxl,  n4);
        n4 = (QDIM * DIN) / 4;   split_f32<<<(n4 + 255) / 256, 256>>>(wq, pwqh, pwql, n4);
        n4 = (KVDIM * DIN) / 4;  split_f32<<<(n4 + 255) / 256, 256>>>(wk, pwkh, pwkl, n4);
        n4 = (KVDIM * DIN) / 4;  split_f32<<<(n4 + 255) / 256, 256>>>(wv, pwvh, pwvl, n4);
        n4 = (DIN * QDIM) / 4;   split_f32<<<(n4 + 255) / 256, 256>>>(wo, pwoh, pwol, n4);
    }

    // QKV projections (HMMA tensor cores)
    gemm_hmma3<<<dim3(QDIM / 128,  M / 128), 256, HSMEM_BYTES>>>(
        pxh, pxl, pwqh, pwql, pq, M, QDIM, DIN);
    gemm_hmma3<<<dim3(KVDIM / 128, M / 128), 256, HSMEM_BYTES>>>(
        pxh, pxl, pwkh, pwkl, pk, M, KVDIM, DIN);
    gemm_hmma3<<<dim3(KVDIM / 128, M / 128), 256, HSMEM_BYTES>>>(
        pxh, pxl, pwvh, pwvl, pv, M, KVDIM, DIN);

    // RMSNorm + RoPE (+ q scaling)
    rms_rope<<<dim3(M, NH + NKV), HD>>>(cosp, sinp, qg, kg);

    // Flash attention (fp32)
    flash_fp32<<<dim3(SS / 64, NH, BB), 256, FLASH_SMEM_FLOATS * sizeof(float)>>>();

    // ctx split + output projection
    {
        int n4 = (M * QDIM) / 4;
        split_f32<<<(n4 + 255) / 256, 256>>>(pctx, pch, pcl, n4);
    }
    gemm_hmma3<<<dim3(QDIM / 128, M / 128), 256, HSMEM_BYTES>>>(
        pch, pcl, pwoh, pwol, out, M, QDIM, DIN);
}

// round 4
// speedup vs baseline: 2.6693x; 1.7060x over previous
#include <cuda_runtime.h>
#include <cuda_bf16.h>
#include <cstdint>
#include <math.h>

// Problem constants
#define BB   2
#define SS   2048
#define DIN  2048
#define NH   8
#define NKV  4
#define HD   256
#define QDIM  (NH*HD)    // 2048
#define KVDIM (NKV*HD)   // 1024
#define SCALING 0.0625f  // 256^-0.5
#define EPS 1e-6f

// ---------------------------------------------------------------------------
// Scratch (device globals)
// ---------------------------------------------------------------------------
__device__ float g_q[(size_t)BB*SS*QDIM];
__device__ float g_k[(size_t)BB*SS*KVDIM];
__device__ float g_v[(size_t)BB*SS*KVDIM];

__device__ __nv_bfloat16 g_xh[(size_t)BB*SS*DIN];
__device__ __nv_bfloat16 g_xl[(size_t)BB*SS*DIN];
__device__ __nv_bfloat16 g_wqh[(size_t)QDIM*DIN];
__device__ __nv_bfloat16 g_wql[(size_t)QDIM*DIN];
__device__ __nv_bfloat16 g_wkh[(size_t)KVDIM*DIN];
__device__ __nv_bfloat16 g_wkl[(size_t)KVDIM*DIN];
__device__ __nv_bfloat16 g_wvh[(size_t)KVDIM*DIN];
__device__ __nv_bfloat16 g_wvl[(size_t)KVDIM*DIN];
__device__ __nv_bfloat16 g_woh[(size_t)DIN*QDIM];
__device__ __nv_bfloat16 g_wol[(size_t)DIN*QDIM];
// post-rmsnorm/rope q,k and v in bf16 hi/lo
__device__ __nv_bfloat16 g_qh[(size_t)BB*SS*QDIM];
__device__ __nv_bfloat16 g_ql[(size_t)BB*SS*QDIM];
__device__ __nv_bfloat16 g_kh[(size_t)BB*SS*KVDIM];
__device__ __nv_bfloat16 g_kl[(size_t)BB*SS*KVDIM];
__device__ __nv_bfloat16 g_vh[(size_t)BB*SS*KVDIM];
__device__ __nv_bfloat16 g_vl[(size_t)BB*SS*KVDIM];
// ctx bf16 hi/lo (written directly by flash)
__device__ __nv_bfloat16 g_ch[(size_t)BB*SS*QDIM];
__device__ __nv_bfloat16 g_cl[(size_t)BB*SS*QDIM];

// ---------------------------------------------------------------------------
// Helpers
// ---------------------------------------------------------------------------
__device__ __forceinline__ uint32_t smem_to_u32(const void* smem_ptr) {
    uint32_t addr;
    asm("{ .reg .u64 tmp; cvta.to.shared.u64 tmp, %1; cvt.u32.u64 %0, tmp; }"
        : "=r"(addr) : "l"(smem_ptr));
    return addr;
}
__device__ __forceinline__ void ldsm_x4(uint32_t& r0, uint32_t& r1,
                                        uint32_t& r2, uint32_t& r3, uint32_t addr) {
    asm volatile("ldmatrix.sync.aligned.m8n8.x4.shared.b16 {%0,%1,%2,%3}, [%4];"
                 : "=r"(r0), "=r"(r1), "=r"(r2), "=r"(r3) : "r"(addr));
}
__device__ __forceinline__ void ldsm_x4t(uint32_t& r0, uint32_t& r1,
                                         uint32_t& r2, uint32_t& r3, uint32_t addr) {
    asm volatile("ldmatrix.sync.aligned.m8n8.x4.trans.shared.b16 {%0,%1,%2,%3}, [%4];"
                 : "=r"(r0), "=r"(r1), "=r"(r2), "=r"(r3) : "r"(addr));
}
__device__ __forceinline__ void ldsm_x2(uint32_t& r0, uint32_t& r1, uint32_t addr) {
    asm volatile("ldmatrix.sync.aligned.m8n8.x2.shared.b16 {%0,%1}, [%2];"
                 : "=r"(r0), "=r"(r1) : "r"(addr));
}
__device__ __forceinline__ void mma_bf16(float* d, const uint32_t* a, const uint32_t* b) {
    asm volatile(
        "mma.sync.aligned.m16n8k16.row.col.f32.bf16.bf16.f32 "
        "{%0,%1,%2,%3}, {%4,%5,%6,%7}, {%8,%9}, {%0,%1,%2,%3};"
        : "+f"(d[0]), "+f"(d[1]), "+f"(d[2]), "+f"(d[3])
        : "r"(a[0]), "r"(a[1]), "r"(a[2]), "r"(a[3]), "r"(b[0]), "r"(b[1]));
}
__device__ __forceinline__ void cp_async16(uint32_t dst, const void* src) {
    asm volatile("cp.async.cg.shared.global [%0], [%1], 16;"
                 :: "r"(dst), "l"(src));
}

__device__ __forceinline__ void split1(float v, unsigned short& h, unsigned short& l) {
    __nv_bfloat16 bh = __float2bfloat16(v);
    float r = v - __bfloat162float(bh);
    __nv_bfloat16 bl = __float2bfloat16(r);
    h = __bfloat16_as_ushort(bh);
    l = __bfloat16_as_ushort(bl);
}
__device__ __forceinline__ void split_pack(float x0, float x1, uint32_t& ph, uint32_t& pl) {
    unsigned short h0, l0, h1, l1;
    split1(x0, h0, l0);
    split1(x1, h1, l1);
    ph = (uint32_t)h0 | ((uint32_t)h1 << 16);
    pl = (uint32_t)l0 | ((uint32_t)l1 << 16);
}

__global__ void split_f32(const float* __restrict__ x,
                          __nv_bfloat16* __restrict__ hi,
                          __nv_bfloat16* __restrict__ lo, int n4) {
    int i = blockIdx.x * blockDim.x + threadIdx.x;
    if (i >= n4) return;
    float4 v = ((const float4*)x)[i];
    ushort4 h, l;
    split1(v.x, h.x, l.x);
    split1(v.y, h.y, l.y);
    split1(v.z, h.z, l.z);
    split1(v.w, h.w, l.w);
    ((ushort4*)hi)[i] = h;
    ((ushort4*)lo)[i] = l;
}

// ---------------------------------------------------------------------------
// HMMA GEMM (NT): C[M,N] = A[M,K] @ B[N,K]^T, bf16 hi/lo 3-term. (R3, passing)
// ---------------------------------------------------------------------------
#define HBK 32
#define HPITCH 80
#define HMAT_BYTES (128 * HPITCH)
#define HSTAGE_BYTES (4 * HMAT_BYTES)
#define HSMEM_BYTES (2 * HSTAGE_BYTES)

__global__ __launch_bounds__(256, 2)
void gemm_hmma3(const __nv_bfloat16* __restrict__ Ah,
                const __nv_bfloat16* __restrict__ Al,
                const __nv_bfloat16* __restrict__ Bh,
                const __nv_bfloat16* __restrict__ Bl,
                float* __restrict__ C, int M, int N, int K) {
    extern __shared__ char smemc[];
    const uint32_t smem = smem_to_u32(smemc);
    const int tid = threadIdx.x;
    const int wid = tid >> 5;
    const int lid = tid & 31;
    const int warp_m = wid >> 2;
    const int warp_n = wid & 3;
    const int m0 = blockIdx.y * 128;
    const int n0 = blockIdx.x * 128;
    const int kchunks = K / HBK;

    const __nv_bfloat16* srcs[4] = {Ah, Al, Bh, Bl};

#define PREFETCH(cc) do {                                                     \
        const int s_ = (cc) & 1;                                              \
        const int k0_ = (cc) * HBK;                                           \
        _Pragma("unroll")                                                     \
        for (int it = 0; it < 8; it++) {                                      \
            int g = tid + 256 * it;                                           \
            int mat = g >> 9;                                                 \
            int idx = g & 511;                                                \
            int r = idx >> 2;                                                 \
            int q = idx & 3;                                                  \
            int rowg = (mat < 2 ? m0 : n0) + r;                               \
            const __nv_bfloat16* src = srcs[mat] + (size_t)rowg * K + k0_ + q * 8; \
            uint32_t dst = smem + s_ * HSTAGE_BYTES + mat * HMAT_BYTES        \
                         + r * HPITCH + q * 16;                               \
            cp_async16(dst, src);                                             \
        }                                                                     \
        asm volatile("cp.async.commit_group;");                               \
    } while (0)

    float acc[4][4][4];
#pragma unroll
    for (int i = 0; i < 4; i++)
#pragma unroll
        for (int j = 0; j < 4; j++)
#pragma unroll
            for (int q = 0; q < 4; q++) acc[i][j][q] = 0.f;

    PREFETCH(0);

    for (int c = 0; c < kchunks; c++) {
        if (c + 1 < kchunks) {
            PREFETCH(c + 1);
            asm volatile("cp.async.wait_group 1;" ::: "memory");
        } else {
            asm volatile("cp.async.wait_group 0;" ::: "memory");
        }
        __syncthreads();

        const uint32_t stage = smem + (c & 1) * HSTAGE_BYTES;
        const uint32_t sAh = stage;
        const uint32_t sAl = stage + HMAT_BYTES;
        const uint32_t sBh = stage + 2 * HMAT_BYTES;
        const uint32_t sBl = stage + 3 * HMAT_BYTES;

#pragma unroll
        for (int k16 = 0; k16 < 2; k16++) {
            const int coff = k16 * 16;
            uint32_t bh[4][2], bl[4][2];
            {
                int i15 = lid & 15;
                int rb = warp_n * 32 + (i15 & 7);
                int kb = coff + ((i15 >> 3) & 1) * 8;
#pragma unroll
                for (int j = 0; j < 4; j++) {
                    uint32_t off = (uint32_t)((rb + j * 8) * HPITCH + kb * 2);
                    ldsm_x2(bh[j][0], bh[j][1], sBh + off);
                    ldsm_x2(bl[j][0], bl[j][1], sBl + off);
                }
            }
            uint32_t a[4][4];
            {
                int ra = warp_m * 64 + (lid & 15);
                int ka = coff + (lid >> 4) * 8;
#pragma unroll
                for (int i = 0; i < 4; i++) {
                    uint32_t off = (uint32_t)((ra + i * 16) * HPITCH + ka * 2);
                    ldsm_x4(a[i][0], a[i][1], a[i][2], a[i][3], sAh + off);
                }
            }
#pragma unroll
            for (int i = 0; i < 4; i++)
#pragma unroll
                for (int j = 0; j < 4; j++) {
                    mma_bf16(acc[i][j], a[i], bh[j]);
                    mma_bf16(acc[i][j], a[i], bl[j]);
                }
            {
                int ra = warp_m * 64 + (lid & 15);
                int ka = coff + (lid >> 4) * 8;
#pragma unroll
                for (int i = 0; i < 4; i++) {
                    uint32_t off = (uint32_t)((ra + i * 16) * HPITCH + ka * 2);
                    ldsm_x4(a[i][0], a[i][1], a[i][2], a[i][3], sAl + off);
                }
            }
#pragma unroll
            for (int i = 0; i < 4; i++)
#pragma unroll
                for (int j = 0; j < 4; j++)
                    mma_bf16(acc[i][j], a[i], bh[j]);
        }
        __syncthreads();
    }

    const int rbase = m0 + warp_m * 64 + (lid >> 2);
    const int cbase = n0 + warp_n * 32 + (lid & 3) * 2;
#pragma unroll
    for (int i = 0; i < 4; i++)
#pragma unroll
        for (int j = 0; j < 4; j++) {
            float* p0 = C + (size_t)(rbase + i * 16) * N + cbase + j * 8;
            float* p1 = C + (size_t)(rbase + i * 16 + 8) * N + cbase + j * 8;
            *(float2*)p0 = make_float2(acc[i][j][0], acc[i][j][1]);
            *(float2*)p1 = make_float2(acc[i][j][2], acc[i][j][3]);
        }
#undef PREFETCH
}

// ---------------------------------------------------------------------------
// Fused RMSNorm + RoPE (+ q scaling) -> bf16 hi/lo outputs.
// ---------------------------------------------------------------------------
__global__ void rms_rope(const float* __restrict__ cosp,
                         const float* __restrict__ sinp,
                         const float* __restrict__ q_gamma,
                         const float* __restrict__ k_gamma) {
    __shared__ float red[8];
    __shared__ float xn_s[HD];

    const int bs = blockIdx.x;
    const int hh = blockIdx.y;
    const int spos = bs & (SS - 1);
    const int d = threadIdx.x;

    const float* ptr;
    __nv_bfloat16 *dh, *dl;
    const float* gamma;
    float scale;
    size_t off;
    if (hh < NH) {
        off = (size_t)bs * QDIM + hh * HD + d;
        ptr = g_q + off;
        dh = g_qh + off;
        dl = g_ql + off;
        gamma = q_gamma;
        scale = SCALING;
    } else {
        off = (size_t)bs * KVDIM + (hh - NH) * HD + d;
        ptr = g_k + off;
        dh = g_kh + off;
        dl = g_kl + off;
        gamma = k_gamma;
        scale = 1.0f;
    }

    float v = *ptr;
    float ss = v * v;
#pragma unroll
    for (int off2 = 16; off2 >= 1; off2 >>= 1)
        ss += __shfl_xor_sync(0xffffffffu, ss, off2);
    if ((d & 31) == 0) red[d >> 5] = ss;
    __syncthreads();
    if (d < 8) {
        float t = red[d];
#pragma unroll
        for (int off2 = 4; off2 >= 1; off2 >>= 1)
            t += __shfl_xor_sync(0xffu, t, off2);
        if (d == 0) red[0] = t;
    }
    __syncthreads();
    float rstd = rsqrtf(red[0] * (1.0f / HD) + EPS);

    float xn = v * rstd * (1.0f + gamma[d]);
    xn_s[d] = xn;
    __syncthreads();
    float rot = (d < HD / 2) ? -xn_s[d + HD / 2] : xn_s[d - HD / 2];
    float out = (xn * cosp[(size_t)spos * HD + d] + rot * sinp[(size_t)spos * HD + d]) * scale;
    unsigned short oh, ol;
    split1(out, oh, ol);
    *dh = __ushort_as_bfloat16(oh);
    *dl = __ushort_as_bfloat16(ol);
}

// ---------------------------------------------------------------------------
// Flash attention with HMMA bf16 hi/lo 3-term. BM=BN=64, D=256.
// 128 threads = 4 warps; warp w owns rows [w*16, w*16+16).
// S = Qh*Kh + Qh*Kl + Ql*Kh ; P kept in registers ; O += Ph*Vh + Ph*Vl + Pl*Vh.
// Pipeline: V load overlaps S-phase, next K load overlaps softmax+PV.
// ---------------------------------------------------------------------------
#define FPITCH 528
#define FTILE (64 * FPITCH)     // 33792
#define FSMEM_BYTES (6 * FTILE) // 202752

__global__ __launch_bounds__(128, 1)
void flash_hmma(const __nv_bfloat16* __restrict__ qh, const __nv_bfloat16* __restrict__ ql,
                const __nv_bfloat16* __restrict__ kh, const __nv_bfloat16* __restrict__ kl,
                const __nv_bfloat16* __restrict__ vh, const __nv_bfloat16* __restrict__ vl,
                __nv_bfloat16* __restrict__ ch, __nv_bfloat16* __restrict__ cl) {
    extern __shared__ char smemc[];
    const uint32_t smem = smem_to_u32(smemc);
    const uint32_t sQh = smem,             sQl = smem + FTILE;
    const uint32_t sKh = smem + 2 * FTILE, sKl = smem + 3 * FTILE;
    const uint32_t sVh = smem + 4 * FTILE, sVl = smem + 5 * FTILE;

    const int qt = blockIdx.x, h = blockIdx.y, b = blockIdx.z;
    const int kvh = h >> 1;
    const int tid = threadIdx.x, wid = tid >> 5, lid = tid & 31;
    const int q0 = qt * 64;

    // Q tiles (one group)
#pragma unroll
    for (int it = 0; it < 16; it++) {
        int g = tid + 128 * it;
        int row = g >> 5, c16 = g & 31;
        size_t go = (size_t)(b * SS + q0 + row) * QDIM + h * HD + c16 * 8;
        uint32_t so = row * FPITCH + c16 * 16;
        cp_async16(sQh + so, qh + go);
        cp_async16(sQl + so, ql + go);
    }
    asm volatile("cp.async.commit_group;");

#define LOAD_KV(dstH, dstL, srcH, srcL, row0) do {                            \
        _Pragma("unroll")                                                     \
        for (int it = 0; it < 16; it++) {                                     \
            int g = tid + 128 * it;                                           \
            int row = g >> 5, c16 = g & 31;                                   \
            size_t go = (size_t)(b * SS + (row0) + row) * KVDIM + kvh * HD + c16 * 8; \
            uint32_t so = row * FPITCH + c16 * 16;                            \
            cp_async16((dstH) + so, (srcH) + go);                             \
            cp_async16((dstL) + so, (srcL) + go);                             \
        }                                                                     \
        asm volatile("cp.async.commit_group;");                               \
    } while (0)

    // K_0
    LOAD_KV(sKh, sKl, kh, kl, 0);

    float o[32][4];
#pragma unroll
    for (int d = 0; d < 32; d++)
#pragma unroll
        for (int c = 0; c < 4; c++) o[d][c] = 0.f;
    float m_[2] = {-1e30f, -1e30f};
    float l_[2] = {0.f, 0.f};

    const int ra = wid * 16 + (lid & 15);          // Q ldsm row
    const int rq = (lid >> 2);                      // local acc row (0..7)

    for (int kt = 0; kt <= qt; kt++) {
        const int k0 = kt * 64;
        asm volatile("cp.async.wait_group 0;" ::: "memory");
        __syncthreads();

        // V_i load (overlaps S-phase)
        LOAD_KV(sVh, sVl, vh, vl, k0);

        // ----- S-phase -----
        float s[8][4];
#pragma unroll
        for (int j = 0; j < 8; j++)
#pragma unroll
            for (int c = 0; c < 4; c++) s[j][c] = 0.f;

#pragma unroll 4
        for (int kc = 0; kc < 16; kc++) {
            uint32_t aH[4], aL[4];
            uint32_t qoff = (uint32_t)(ra * FPITCH + (kc * 16 + (lid >> 4) * 8) * 2);
            ldsm_x4(aH[0], aH[1], aH[2], aH[3], sQh + qoff);
            ldsm_x4(aL[0], aL[1], aL[2], aL[3], sQl + qoff);
#pragma unroll
            for (int p = 0; p < 4; p++) {
                uint32_t boff = (uint32_t)(
                    (p * 16 + ((lid >> 4) & 1) * 8 + (lid & 7)) * FPITCH
                    + (kc * 16 + ((lid >> 3) & 1) * 8) * 2);
                uint32_t bh[4], bl[4];
                ldsm_x4(bh[0], bh[1], bh[2], bh[3], sKh + boff);
                ldsm_x4(bl[0], bl[1], bl[2], bl[3], sKl + boff);
                mma_bf16(s[2 * p],     aH, &bh[0]);
                mma_bf16(s[2 * p + 1], aH, &bh[2]);
                mma_bf16(s[2 * p],     aH, &bl[0]);
                mma_bf16(s[2 * p + 1], aH, &bl[2]);
                mma_bf16(s[2 * p],     aL, &bh[0]);
                mma_bf16(s[2 * p + 1], aL, &bh[2]);
            }
        }

        __syncthreads();                 // all warps done reading K tile
        if (kt < qt) {                   // prefetch next K (overlaps softmax+PV)
            LOAD_KV(sKh, sKl, kh, kl, k0 + 64);
        }

        // ----- mask (diagonal tile) -----
        if (kt == qt) {
#pragma unroll
            for (int j = 0; j < 8; j++)
#pragma unroll
                for (int c = 0; c < 4; c++) {
                    int col = j * 8 + (lid & 3) * 2 + (c & 1);
                    int row = wid * 16 + rq + (c >> 1) * 8;
                    if (col > row) s[j][c] = -1e30f;
                }
        }

        // ----- online softmax (rows r, r+8 per thread) -----
        float alpha[2];
#pragma unroll
        for (int hh = 0; hh < 2; hh++) {
            float mx = -1e30f;
#pragma unroll
            for (int j = 0; j < 8; j++)
                mx = fmaxf(mx, fmaxf(s[j][2 * hh], s[j][2 * hh + 1]));
            mx = fmaxf(mx, __shfl_xor_sync(0xffffffffu, mx, 1));
            mx = fmaxf(mx, __shfl_xor_sync(0xffffffffu, mx, 2));
            float mnew = fmaxf(m_[hh], mx);
            alpha[hh] = __expf(m_[hh] - mnew);
            m_[hh] = mnew;
            float sum = 0.f;
#pragma unroll
            for (int j = 0; j < 8; j++) {
                float p0 = __expf(s[j][2 * hh] - mnew);
                float p1 = __expf(s[j][2 * hh + 1] - mnew);
                s[j][2 * hh] = p0;
                s[j][2 * hh + 1] = p1;
                sum += p0 + p1;
            }
            sum += __shfl_xor_sync(0xffffffffu, sum, 1);
            sum += __shfl_xor_sync(0xffffffffu, sum, 2);
            l_[hh] = l_[hh] * alpha[hh] + sum;
        }
        // rescale O
#pragma unroll
        for (int d = 0; d < 32; d++) {
            o[d][0] *= alpha[0];
            o[d][1] *= alpha[0];
            o[d][2] *= alpha[1];
            o[d][3] *= alpha[1];
        }

        // ----- P -> bf16 hi/lo fragments (registers) -----
        uint32_t pah0[8], pah1[8], pal0[8], pal1[8];
#pragma unroll
        for (int j = 0; j < 8; j++) {
            split_pack(s[j][0], s[j][1], pah0[j], pal0[j]);
            split_pack(s[j][2], s[j][3], pah1[j], pal1[j]);
        }

        // wait V (pending groups: V_i [, K_{i+1}])
        if (kt < qt) {
            asm volatile("cp.async.wait_group 1;" ::: "memory");
        } else {
            asm volatile("cp.async.wait_group 0;" ::: "memory");
        }
        __syncthreads();

        // ----- PV phase -----
#pragma unroll
        for (int kc = 0; kc < 4; kc++) {
            uint32_t aPh[4] = {pah0[2 * kc], pah1[2 * kc], pah0[2 * kc + 1], pah1[2 * kc + 1]};
            uint32_t aPl[4] = {pal0[2 * kc], pal1[2 * kc], pal0[2 * kc + 1], pal1[2 * kc + 1]};
#pragma unroll
            for (int dp = 0; dp < 16; dp++) {
                uint32_t voff = (uint32_t)(
                    (kc * 16 + ((lid >> 3) & 1) * 8 + (lid & 7)) * FPITCH
                    + (dp * 16 + ((lid >> 4) & 1) * 8) * 2);
                uint32_t bh[4], bl[4];
                ldsm_x4t(bh[0], bh[1], bh[2], bh[3], sVh + voff);
                mma_bf16(o[2 * dp],     aPh, &bh[0]);
                mma_bf16(o[2 * dp + 1], aPh, &bh[2]);
                mma_bf16(o[2 * dp],     aPl, &bh[0]);
                mma_bf16(o[2 * dp + 1], aPl, &bh[2]);
                ldsm_x4t(bl[0], bl[1], bl[2], bl[3], sVl + voff);
                mma_bf16(o[2 * dp],     aPh, &bl[0]);
                mma_bf16(o[2 * dp + 1], aPh, &bl[2]);
            }
        }
    }

    // ----- epilogue: normalize, write ctx as bf16 hi/lo -----
    float inv[2] = {1.f / l_[0], 1.f / l_[1]};
#pragma unroll
    for (int hh = 0; hh < 2; hh++) {
        int row = q0 + wid * 16 + rq + 8 * hh;
        size_t base = (size_t)(b * SS + row) * QDIM + h * HD;
#pragma unroll
        for (int d = 0; d < 32; d++) {
            int col = d * 8 + (lid & 3) * 2;
            float v0 = o[d][2 * hh] * inv[hh];
            float v1 = o[d][2 * hh + 1] * inv[hh];
            uint32_t ph, pl;
            split_pack(v0, v1, ph, pl);
            *(uint32_t*)(ch + base + col) = ph;
            *(uint32_t*)(cl + base + col) = pl;
        }
    }
#undef LOAD_KV
}

// ---------------------------------------------------------------------------
// launch
// ---------------------------------------------------------------------------
extern "C" void kernel_launch(void* const* d_in, const int* in_sizes, int n_in,
                              void* d_out, int out_size) {
    const float* x    = (const float*)d_in[0];
    const float* cosp = (const float*)d_in[2];
    const float* sinp = (const float*)d_in[3];
    const float* wq   = (const float*)d_in[4];
    const float* wk   = (const float*)d_in[5];
    const float* wv   = (const float*)d_in[6];
    const float* wo   = (const float*)d_in[7];
    const float* qg   = (const float*)d_in[8];
    const float* kg   = (const float*)d_in[9];
    float* out = (float*)d_out;

    float *pq, *pk, *pv;
    __nv_bfloat16 *pxh, *pxl, *pwqh, *pwql, *pwkh, *pwkl, *pwvh, *pwvl, *pwoh, *pwol;
    __nv_bfloat16 *pqh, *pql, *pkh, *pkl, *pvh, *pvl, *pch, *pcl;
    cudaGetSymbolAddress((void**)&pq,   g_q);
    cudaGetSymbolAddress((void**)&pk,   g_k);
    cudaGetSymbolAddress((void**)&pv,   g_v);
    cudaGetSymbolAddress((void**)&pxh,  g_xh);
    cudaGetSymbolAddress((void**)&pxl,  g_xl);
    cudaGetSymbolAddress((void**)&pwqh, g_wqh);
    cudaGetSymbolAddress((void**)&pwql, g_wql);
    cudaGetSymbolAddress((void**)&pwkh, g_wkh);
    cudaGetSymbolAddress((void**)&pwkl, g_wkl);
    cudaGetSymbolAddress((void**)&pwvh, g_wvh);
    cudaGetSymbolAddress((void**)&pwvl, g_wvl);
    cudaGetSymbolAddress((void**)&pwoh, g_woh);
    cudaGetSymbolAddress((void**)&pwol, g_wol);
    cudaGetSymbolAddress((void**)&pqh,  g_qh);
    cudaGetSymbolAddress((void**)&pql,  g_ql);
    cudaGetSymbolAddress((void**)&pkh,  g_kh);
    cudaGetSymbolAddress((void**)&pkl,  g_kl);
    cudaGetSymbolAddress((void**)&pvh,  g_vh);
    cudaGetSymbolAddress((void**)&pvl,  g_vl);
    cudaGetSymbolAddress((void**)&pch,  g_ch);
    cudaGetSymbolAddress((void**)&pcl,  g_cl);

    const int M = BB * SS;   // 4096

    cudaFuncSetAttribute(gemm_hmma3, cudaFuncAttributeMaxDynamicSharedMemorySize,
                         HSMEM_BYTES);
    cudaFuncSetAttribute(flash_hmma, cudaFuncAttributeMaxDynamicSharedMemorySize,
                         FSMEM_BYTES);

    // splits (inputs + weights)
    {
        int n4;
        n4 = (M * DIN) / 4;      split_f32<<<(n4 + 255) / 256, 256>>>(x,  pxh,  pxl,  n4);
        n4 = (QDIM * DIN) / 4;   split_f32<<<(n4 + 255) / 256, 256>>>(wq, pwqh, pwql, n4);
        n4 = (KVDIM * DIN) / 4;  split_f32<<<(n4 + 255) / 256, 256>>>(wk, pwkh, pwkl, n4);
        n4 = (KVDIM * DIN) / 4;  split_f32<<<(n4 + 255) / 256, 256>>>(wv, pwvh, pwvl, n4);
        n4 = (DIN * QDIM) / 4;   split_f32<<<(n4 + 255) / 256, 256>>>(wo, pwoh, pwol, n4);
    }

    // QKV projections
    gemm_hmma3<<<dim3(QDIM / 128,  M / 128), 256, HSMEM_BYTES>>>(
        pxh, pxl, pwqh, pwql, pq, M, QDIM, DIN);
    gemm_hmma3<<<dim3(KVDIM / 128, M / 128), 256, HSMEM_BYTES>>>(
        pxh, pxl, pwkh, pwkl, pk, M, KVDIM, DIN);
    gemm_hmma3<<<dim3(KVDIM / 128, M / 128), 256, HSMEM_BYTES>>>(
        pxh, pxl, pwvh, pwvl, pv, M, KVDIM, DIN);

    // RMSNorm + RoPE -> bf16 hi/lo q,k ; split v
    rms_rope<<<dim3(M, NH + NKV), HD>>>(cosp, sinp, qg, kg);
    {
        int n4 = (M * KVDIM) / 4;
        split_f32<<<(n4 + 255) / 256, 256>>>(pv, pvh, pvl, n4);
    }

    // Flash attention (HMMA)
    flash_hmma<<<dim3(SS / 64, NH, BB), 128, FSMEM_BYTES>>>(
        pqh, pql, pkh, pkl, pvh, pvl, pch, pcl);

    // Output projection
    gemm_hmma3<<<dim3(QDIM / 128, M / 128), 256, HSMEM_BYTES>>>(
        pch, pcl, pwoh, pwol, out, M, QDIM, DIN);
}

// round 5
// speedup vs baseline: 6.2882x; 2.3558x over previous
#include <cuda_runtime.h>
#include <cuda_fp16.h>
#include <cstdint>
#include <math.h>

// Problem constants
#define BB   2
#define SS   2048
#define DIN  2048
#define NH   8
#define NKV  4
#define HD   256
#define QDIM  (NH*HD)    // 2048
#define KVDIM (NKV*HD)   // 1024
#define SCALING 0.0625f  // 256^-0.5
#define EPS 1e-6f

// ---------------------------------------------------------------------------
// Scratch (device globals)
// ---------------------------------------------------------------------------
__device__ float g_q[(size_t)BB*SS*QDIM];
__device__ float g_k[(size_t)BB*SS*KVDIM];
__device__ float g_v[(size_t)BB*SS*KVDIM];

__device__ __half g_xh[(size_t)BB*SS*DIN];
__device__ __half g_wqh[(size_t)QDIM*DIN];
__device__ __half g_wkh[(size_t)KVDIM*DIN];
__device__ __half g_wvh[(size_t)KVDIM*DIN];
__device__ __half g_woh[(size_t)DIN*QDIM];
__device__ __half g_qh[(size_t)BB*SS*QDIM];
__device__ __half g_kh[(size_t)BB*SS*KVDIM];
__device__ __half g_vh[(size_t)BB*SS*KVDIM];
__device__ __half g_ch[(size_t)BB*SS*QDIM];

// ---------------------------------------------------------------------------
// Helpers
// ---------------------------------------------------------------------------
__device__ __forceinline__ uint32_t smem_to_u32(const void* smem_ptr) {
    uint32_t addr;
    asm("{ .reg .u64 tmp; cvta.to.shared.u64 tmp, %1; cvt.u32.u64 %0, tmp; }"
        : "=r"(addr) : "l"(smem_ptr));
    return addr;
}
__device__ __forceinline__ void ldsm_x4(uint32_t& r0, uint32_t& r1,
                                        uint32_t& r2, uint32_t& r3, uint32_t addr) {
    asm volatile("ldmatrix.sync.aligned.m8n8.x4.shared.b16 {%0,%1,%2,%3}, [%4];"
                 : "=r"(r0), "=r"(r1), "=r"(r2), "=r"(r3) : "r"(addr));
}
__device__ __forceinline__ void ldsm_x4t(uint32_t& r0, uint32_t& r1,
                                         uint32_t& r2, uint32_t& r3, uint32_t addr) {
    asm volatile("ldmatrix.sync.aligned.m8n8.x4.trans.shared.b16 {%0,%1,%2,%3}, [%4];"
                 : "=r"(r0), "=r"(r1), "=r"(r2), "=r"(r3) : "r"(addr));
}
__device__ __forceinline__ void ldsm_x2(uint32_t& r0, uint32_t& r1, uint32_t addr) {
    asm volatile("ldmatrix.sync.aligned.m8n8.x2.shared.b16 {%0,%1}, [%2];"
                 : "=r"(r0), "=r"(r1) : "r"(addr));
}
__device__ __forceinline__ void mma_f16(float* d, const uint32_t* a, const uint32_t* b) {
    asm volatile(
        "mma.sync.aligned.m16n8k16.row.col.f32.f16.f16.f32 "
        "{%0,%1,%2,%3}, {%4,%5,%6,%7}, {%8,%9}, {%0,%1,%2,%3};"
        : "+f"(d[0]), "+f"(d[1]), "+f"(d[2]), "+f"(d[3])
        : "r"(a[0]), "r"(a[1]), "r"(a[2]), "r"(a[3]), "r"(b[0]), "r"(b[1]));
}
__device__ __forceinline__ void cp_async16(uint32_t dst, const void* src) {
    asm volatile("cp.async.cg.shared.global [%0], [%1], 16;"
                 :: "r"(dst), "l"(src));
}
__device__ __forceinline__ uint32_t pack_h2(float x0, float x1) {
    __half2 h = __floats2half2_rn(x0, x1);
    return *(uint32_t*)&h;
}

// fp32 -> fp16 convert, vectorized by 4
__global__ void cvt_f16(const float* __restrict__ x, __half* __restrict__ out, int n4) {
    int i = blockIdx.x * blockDim.x + threadIdx.x;
    if (i >= n4) return;
    float4 v = ((const float4*)x)[i];
    uint2 r;
    r.x = pack_h2(v.x, v.y);
    r.y = pack_h2(v.z, v.w);
    ((uint2*)out)[i] = r;
}

// ---------------------------------------------------------------------------
// HMMA GEMM (NT, fp16 single-term): C[M,N] = A[M,K] @ B[N,K]^T.
// Tile 128x128, BK=32, 8 warps (2x4), warp tile 64x32, m16n8k16.
// smem: 2 stages x {A, B}, each 128 rows x 80B pitch. cp.async double-buffered.
// ---------------------------------------------------------------------------
#define HBK 32
#define HPITCH 80
#define HMAT_BYTES (128 * HPITCH)      // 10240
#define HSTAGE_BYTES (2 * HMAT_BYTES)  // 20480
#define HSMEM_BYTES (2 * HSTAGE_BYTES) // 40960

__global__ __launch_bounds__(256, 2)
void gemm_f16(const __half* __restrict__ A, const __half* __restrict__ B,
              float* __restrict__ C, int M, int N, int K) {
    extern __shared__ char smemc[];
    const uint32_t smem = smem_to_u32(smemc);
    const int tid = threadIdx.x;
    const int wid = tid >> 5;
    const int lid = tid & 31;
    const int warp_m = wid >> 2;
    const int warp_n = wid & 3;
    const int m0 = blockIdx.y * 128;
    const int n0 = blockIdx.x * 128;
    const int kchunks = K / HBK;

#define PREFETCH(cc) do {                                                     \
        const int s_ = (cc) & 1;                                              \
        const int k0_ = (cc) * HBK;                                           \
        _Pragma("unroll")                                                     \
        for (int it = 0; it < 4; it++) {                                      \
            int g = tid + 256 * it;                                           \
            int mat = g >> 9;                                                 \
            int idx = g & 511;                                                \
            int r = idx >> 2;                                                 \
            int q = idx & 3;                                                  \
            int rowg = (mat == 0 ? m0 : n0) + r;                              \
            const __half* src = (mat == 0 ? A : B) + (size_t)rowg * K + k0_ + q * 8; \
            uint32_t dst = smem + s_ * HSTAGE_BYTES + mat * HMAT_BYTES        \
                         + r * HPITCH + q * 16;                               \
            cp_async16(dst, src);                                             \
        }                                                                     \
        asm volatile("cp.async.commit_group;");                               \
    } while (0)

    float acc[4][4][4];
#pragma unroll
    for (int i = 0; i < 4; i++)
#pragma unroll
        for (int j = 0; j < 4; j++)
#pragma unroll
            for (int q = 0; q < 4; q++) acc[i][j][q] = 0.f;

    PREFETCH(0);

    for (int c = 0; c < kchunks; c++) {
        if (c + 1 < kchunks) {
            PREFETCH(c + 1);
            asm volatile("cp.async.wait_group 1;" ::: "memory");
        } else {
            asm volatile("cp.async.wait_group 0;" ::: "memory");
        }
        __syncthreads();

        const uint32_t stage = smem + (c & 1) * HSTAGE_BYTES;
        const uint32_t sA = stage;
        const uint32_t sB = stage + HMAT_BYTES;

#pragma unroll
        for (int k16 = 0; k16 < 2; k16++) {
            const int coff = k16 * 16;
            uint32_t b[4][2];
            {
                int i15 = lid & 15;
                int rb = warp_n * 32 + (i15 & 7);
                int kb = coff + ((i15 >> 3) & 1) * 8;
#pragma unroll
                for (int j = 0; j < 4; j++) {
                    uint32_t off = (uint32_t)((rb + j * 8) * HPITCH + kb * 2);
                    ldsm_x2(b[j][0], b[j][1], sB + off);
                }
            }
            uint32_t a[4][4];
            {
                int ra = warp_m * 64 + (lid & 15);
                int ka = coff + (lid >> 4) * 8;
#pragma unroll
                for (int i = 0; i < 4; i++) {
                    uint32_t off = (uint32_t)((ra + i * 16) * HPITCH + ka * 2);
                    ldsm_x4(a[i][0], a[i][1], a[i][2], a[i][3], sA + off);
                }
            }
#pragma unroll
            for (int i = 0; i < 4; i++)
#pragma unroll
                for (int j = 0; j < 4; j++)
                    mma_f16(acc[i][j], a[i], b[j]);
        }
        __syncthreads();
    }

    const int rbase = m0 + warp_m * 64 + (lid >> 2);
    const int cbase = n0 + warp_n * 32 + (lid & 3) * 2;
#pragma unroll
    for (int i = 0; i < 4; i++)
#pragma unroll
        for (int j = 0; j < 4; j++) {
            float* p0 = C + (size_t)(rbase + i * 16) * N + cbase + j * 8;
            float* p1 = C + (size_t)(rbase + i * 16 + 8) * N + cbase + j * 8;
            *(float2*)p0 = make_float2(acc[i][j][0], acc[i][j][1]);
            *(float2*)p1 = make_float2(acc[i][j][2], acc[i][j][3]);
        }
#undef PREFETCH
}

// ---------------------------------------------------------------------------
// Fused RMSNorm + RoPE (+ q scaling) -> fp16 outputs.
// ---------------------------------------------------------------------------
__global__ void rms_rope(const float* __restrict__ cosp,
                         const float* __restrict__ sinp,
                         const float* __restrict__ q_gamma,
                         const float* __restrict__ k_gamma) {
    __shared__ float red[8];
    __shared__ float xn_s[HD];

    const int bs = blockIdx.x;
    const int hh = blockIdx.y;
    const int spos = bs & (SS - 1);
    const int d = threadIdx.x;

    const float* ptr;
    __half* dh;
    const float* gamma;
    float scale;
    size_t off;
    if (hh < NH) {
        off = (size_t)bs * QDIM + hh * HD + d;
        ptr = g_q + off;
        dh = g_qh + off;
        gamma = q_gamma;
        scale = SCALING;
    } else {
        off = (size_t)bs * KVDIM + (hh - NH) * HD + d;
        ptr = g_k + off;
        dh = g_kh + off;
        gamma = k_gamma;
        scale = 1.0f;
    }

    float v = *ptr;
    float ss = v * v;
#pragma unroll
    for (int off2 = 16; off2 >= 1; off2 >>= 1)
        ss += __shfl_xor_sync(0xffffffffu, ss, off2);
    if ((d & 31) == 0) red[d >> 5] = ss;
    __syncthreads();
    if (d < 8) {
        float t = red[d];
#pragma unroll
        for (int off2 = 4; off2 >= 1; off2 >>= 1)
            t += __shfl_xor_sync(0xffu, t, off2);
        if (d == 0) red[0] = t;
    }
    __syncthreads();
    float rstd = rsqrtf(red[0] * (1.0f / HD) + EPS);

    float xn = v * rstd * (1.0f + gamma[d]);
    xn_s[d] = xn;
    __syncthreads();
    float rot = (d < HD / 2) ? -xn_s[d + HD / 2] : xn_s[d - HD / 2];
    float out = (xn * cosp[(size_t)spos * HD + d] + rot * sinp[(size_t)spos * HD + d]) * scale;
    *dh = __float2half(out);
}

// ---------------------------------------------------------------------------
// Flash attention, fp16 single-term HMMA. BM=BN=64, D=256.
// 128 threads = 4 warps; warp w owns rows [w*16, w*16+16).
// P kept in registers. Pipeline: V load overlaps S-phase, next K overlaps PV.
// ---------------------------------------------------------------------------
#define FPITCH 528
#define FTILE (64 * FPITCH)     // 33792
#define FSMEM_BYTES (3 * FTILE) // 101376

__global__ __launch_bounds__(128)
void flash_f16(const __half* __restrict__ qh, const __half* __restrict__ kh,
               const __half* __restrict__ vh, __half* __restrict__ ch) {
    extern __shared__ char smemc[];
    const uint32_t smem = smem_to_u32(smemc);
    const uint32_t sQ = smem;
    const uint32_t sK = smem + FTILE;
    const uint32_t sV = smem + 2 * FTILE;

    const int qt = blockIdx.x, h = blockIdx.y, b = blockIdx.z;
    const int kvh = h >> 1;
    const int tid = threadIdx.x, wid = tid >> 5, lid = tid & 31;
    const int q0 = qt * 64;

    // Q tile
#pragma unroll
    for (int it = 0; it < 16; it++) {
        int g = tid + 128 * it;
        int row = g >> 5, c16 = g & 31;
        size_t go = (size_t)(b * SS + q0 + row) * QDIM + h * HD + c16 * 8;
        cp_async16(sQ + row * FPITCH + c16 * 16, qh + go);
    }
    asm volatile("cp.async.commit_group;");

#define LOAD_KV(dst, src, row0) do {                                          \
        _Pragma("unroll")                                                     \
        for (int it = 0; it < 16; it++) {                                     \
            int g = tid + 128 * it;                                           \
            int row = g >> 5, c16 = g & 31;                                   \
            size_t go = (size_t)(b * SS + (row0) + row) * KVDIM + kvh * HD + c16 * 8; \
            cp_async16((dst) + row * FPITCH + c16 * 16, (src) + go);          \
        }                                                                     \
        asm volatile("cp.async.commit_group;");                               \
    } while (0)

    LOAD_KV(sK, kh, 0);

    float o[32][4];
#pragma unroll
    for (int d = 0; d < 32; d++)
#pragma unroll
        for (int c = 0; c < 4; c++) o[d][c] = 0.f;
    float m_[2] = {-1e30f, -1e30f};
    float l_[2] = {0.f, 0.f};

    const int ra = wid * 16 + (lid & 15);
    const int rq = (lid >> 2);

    for (int kt = 0; kt <= qt; kt++) {
        const int k0 = kt * 64;
        asm volatile("cp.async.wait_group 0;" ::: "memory");
        __syncthreads();

        LOAD_KV(sV, vh, k0);   // overlaps S-phase

        // ----- S-phase -----
        float s[8][4];
#pragma unroll
        for (int j = 0; j < 8; j++)
#pragma unroll
            for (int c = 0; c < 4; c++) s[j][c] = 0.f;

#pragma unroll 4
        for (int kc = 0; kc < 16; kc++) {
            uint32_t a[4];
            uint32_t qoff = (uint32_t)(ra * FPITCH + (kc * 16 + (lid >> 4) * 8) * 2);
            ldsm_x4(a[0], a[1], a[2], a[3], sQ + qoff);
#pragma unroll
            for (int p = 0; p < 4; p++) {
                uint32_t boff = (uint32_t)(
                    (p * 16 + ((lid >> 4) & 1) * 8 + (lid & 7)) * FPITCH
                    + (kc * 16 + ((lid >> 3) & 1) * 8) * 2);
                uint32_t bb[4];
                ldsm_x4(bb[0], bb[1], bb[2], bb[3], sK + boff);
                mma_f16(s[2 * p],     a, &bb[0]);
                mma_f16(s[2 * p + 1], a, &bb[2]);
            }
        }

        __syncthreads();
        if (kt < qt) LOAD_KV(sK, kh, k0 + 64);   // overlaps softmax + PV

        // ----- mask -----
        if (kt == qt) {
#pragma unroll
            for (int j = 0; j < 8; j++)
#pragma unroll
                for (int c = 0; c < 4; c++) {
                    int col = j * 8 + (lid & 3) * 2 + (c & 1);
                    int row = wid * 16 + rq + (c >> 1) * 8;
                    if (col > row) s[j][c] = -1e30f;
                }
        }

        // ----- online softmax -----
        float alpha[2];
#pragma unroll
        for (int hh = 0; hh < 2; hh++) {
            float mx = -1e30f;
#pragma unroll
            for (int j = 0; j < 8; j++)
                mx = fmaxf(mx, fmaxf(s[j][2 * hh], s[j][2 * hh + 1]));
            mx = fmaxf(mx, __shfl_xor_sync(0xffffffffu, mx, 1));
            mx = fmaxf(mx, __shfl_xor_sync(0xffffffffu, mx, 2));
            float mnew = fmaxf(m_[hh], mx);
            alpha[hh] = __expf(m_[hh] - mnew);
            m_[hh] = mnew;
            float sum = 0.f;
#pragma unroll
            for (int j = 0; j < 8; j++) {
                float p0 = __expf(s[j][2 * hh] - mnew);
                float p1 = __expf(s[j][2 * hh + 1] - mnew);
                s[j][2 * hh] = p0;
                s[j][2 * hh + 1] = p1;
                sum += p0 + p1;
            }
            sum += __shfl_xor_sync(0xffffffffu, sum, 1);
            sum += __shfl_xor_sync(0xffffffffu, sum, 2);
            l_[hh] = l_[hh] * alpha[hh] + sum;
        }
#pragma unroll
        for (int d = 0; d < 32; d++) {
            o[d][0] *= alpha[0];
            o[d][1] *= alpha[0];
            o[d][2] *= alpha[1];
            o[d][3] *= alpha[1];
        }

        // ----- P -> fp16 fragments (registers) -----
        uint32_t p0[8], p1[8];
#pragma unroll
        for (int j = 0; j < 8; j++) {
            p0[j] = pack_h2(s[j][0], s[j][1]);
            p1[j] = pack_h2(s[j][2], s[j][3]);
        }

        if (kt < qt) {
            asm volatile("cp.async.wait_group 1;" ::: "memory");
        } else {
            asm volatile("cp.async.wait_group 0;" ::: "memory");
        }
        __syncthreads();

        // ----- PV phase -----
#pragma unroll
        for (int kc = 0; kc < 4; kc++) {
            uint32_t aP[4] = {p0[2 * kc], p1[2 * kc], p0[2 * kc + 1], p1[2 * kc + 1]};
#pragma unroll
            for (int dp = 0; dp < 16; dp++) {
                uint32_t voff = (uint32_t)(
                    (kc * 16 + ((lid >> 3) & 1) * 8 + (lid & 7)) * FPITCH
                    + (dp * 16 + ((lid >> 4) & 1) * 8) * 2);
                uint32_t bb[4];
                ldsm_x4t(bb[0], bb[1], bb[2], bb[3], sV + voff);
                mma_f16(o[2 * dp],     aP, &bb[0]);
                mma_f16(o[2 * dp + 1], aP, &bb[2]);
            }
        }
    }

    // ----- epilogue -----
    float inv[2] = {1.f / l_[0], 1.f / l_[1]};
#pragma unroll
    for (int hh = 0; hh < 2; hh++) {
        int row = q0 + wid * 16 + rq + 8 * hh;
        size_t base = (size_t)(b * SS + row) * QDIM + h * HD;
#pragma unroll
        for (int d = 0; d < 32; d++) {
            int col = d * 8 + (lid & 3) * 2;
            float v0 = o[d][2 * hh] * inv[hh];
            float v1 = o[d][2 * hh + 1] * inv[hh];
            *(uint32_t*)(ch + base + col) = pack_h2(v0, v1);
        }
    }
#undef LOAD_KV
}

// ---------------------------------------------------------------------------
// launch
// ---------------------------------------------------------------------------
extern "C" void kernel_launch(void* const* d_in, const int* in_sizes, int n_in,
                              void* d_out, int out_size) {
    const float* x    = (const float*)d_in[0];
    const float* cosp = (const float*)d_in[2];
    const float* sinp = (const float*)d_in[3];
    const float* wq   = (const float*)d_in[4];
    const float* wk   = (const float*)d_in[5];
    const float* wv   = (const float*)d_in[6];
    const float* wo   = (const float*)d_in[7];
    const float* qg   = (const float*)d_in[8];
    const float* kg   = (const float*)d_in[9];
    float* out = (float*)d_out;

    float *pq, *pk, *pv;
    __half *pxh, *pwqh, *pwkh, *pwvh, *pwoh, *pqh, *pkh, *pvh, *pch;
    cudaGetSymbolAddress((void**)&pq,   g_q);
    cudaGetSymbolAddress((void**)&pk,   g_k);
    cudaGetSymbolAddress((void**)&pv,   g_v);
    cudaGetSymbolAddress((void**)&pxh,  g_xh);
    cudaGetSymbolAddress((void**)&pwqh, g_wqh);
    cudaGetSymbolAddress((void**)&pwkh, g_wkh);
    cudaGetSymbolAddress((void**)&pwvh, g_wvh);
    cudaGetSymbolAddress((void**)&pwoh, g_woh);
    cudaGetSymbolAddress((void**)&pqh,  g_qh);
    cudaGetSymbolAddress((void**)&pkh,  g_kh);
    cudaGetSymbolAddress((void**)&pvh,  g_vh);
    cudaGetSymbolAddress((void**)&pch,  g_ch);

    const int M = BB * SS;   // 4096

    cudaFuncSetAttribute(gemm_f16, cudaFuncAttributeMaxDynamicSharedMemorySize,
                         HSMEM_BYTES);
    cudaFuncSetAttribute(flash_f16, cudaFuncAttributeMaxDynamicSharedMemorySize,
                         FSMEM_BYTES);

    // fp32 -> fp16 converts
    {
        int n4;
        n4 = (M * DIN) / 4;      cvt_f16<<<(n4 + 255) / 256, 256>>>(x,  pxh,  n4);
        n4 = (QDIM * DIN) / 4;   cvt_f16<<<(n4 + 255) / 256, 256>>>(wq, pwqh, n4);
        n4 = (KVDIM * DIN) / 4;  cvt_f16<<<(n4 + 255) / 256, 256>>>(wk, pwkh, n4);
        n4 = (KVDIM * DIN) / 4;  cvt_f16<<<(n4 + 255) / 256, 256>>>(wv, pwvh, n4);
        n4 = (DIN * QDIM) / 4;   cvt_f16<<<(n4 + 255) / 256, 256>>>(wo, pwoh, n4);
    }

    // QKV projections
    gemm_f16<<<dim3(QDIM / 128,  M / 128), 256, HSMEM_BYTES>>>(pxh, pwqh, pq, M, QDIM,  DIN);
    gemm_f16<<<dim3(KVDIM / 128, M / 128), 256, HSMEM_BYTES>>>(pxh, pwkh, pk, M, KVDIM, DIN);
    gemm_f16<<<dim3(KVDIM / 128, M / 128), 256, HSMEM_BYTES>>>(pxh, pwvh, pv, M, KVDIM, DIN);

    // RMSNorm + RoPE -> fp16 q,k ; convert v
    rms_rope<<<dim3(M, NH + NKV), HD>>>(cosp, sinp, qg, kg);
    {
        int n4 = (M * KVDIM) / 4;
        cvt_f16<<<(n4 + 255) / 256, 256>>>(pv, pvh, n4);
    }

    // Flash attention
    flash_f16<<<dim3(SS / 64, NH, BB), 128, FSMEM_BYTES>>>(pqh, pkh, pvh, pch);

    // Output projection
    gemm_f16<<<dim3(QDIM / 128, M / 128), 256, HSMEM_BYTES>>>(pch, pwoh, out, M, QDIM, DIN);
}